// round 13
// baseline (speedup 1.0000x reference)
#include <cuda_runtime.h>
#include <cstdint>

#define T_LEN 512
#define BATCH 2048
#define DIN   128
#define HID   16
#define NG    64            // 4 gates * HID
#define FANIN 144           // DIN + HID
#define CHUNK 32            // timesteps per sync chunk
#define NCHUNK (T_LEN / CHUNK)                  // 16
#define TILE_M 64
#define TILES_PER_CHUNK (CHUNK * BATCH / TILE_M)   // 1024
#define TOTAL_TILES (T_LEN * BATCH / TILE_M)       // 16384
#define RBLK  128           // recur blocks: 8 warps x 2 rows = 16 rows each
#define GPERS 168           // persistent gemm blocks
#define NBLK  (RBLK + GPERS)   // 296 = 148 SMs x 2 blocks

// Scratch
__device__ float g_pre[(size_t)T_LEN * BATCH * NG];     // 256 MB
__device__ unsigned char g_Bh[NG * DIN * 2];            // B hi, [n][k] bf16
__device__ unsigned char g_Bl[NG * DIN * 2];            // B lo, [n][k] bf16
__device__ unsigned g_ticket;                           // gemm tile ticket
__device__ unsigned g_done[NCHUNK];                     // per-chunk tiles done

// ======================= helpers =======================
__device__ __forceinline__ uint32_t smem_u32(const void* p) {
    uint32_t a;
    asm("{ .reg .u64 t; cvta.to.shared.u64 t, %1; cvt.u32.u64 %0, t; }" : "=r"(a) : "l"(p));
    return a;
}
__device__ __forceinline__ unsigned ldacq(const unsigned* p) {
    unsigned v;
    asm volatile("ld.acquire.gpu.global.b32 %0, [%1];" : "=r"(v) : "l"(p));
    return v;
}
// cvt pair: LOWER half = first value argument
#define CVT2(result, a, b) \
    asm("cvt.rn.satfinite.bf16x2.f32 %0, %1, %2;" : "=r"(result) : "f"(b), "f"(a))

#define LDMX4(r0, r1, r2, r3, addr) \
    asm volatile("ldmatrix.sync.aligned.m8n8.x4.shared.b16 {%0,%1,%2,%3}, [%4];" \
        : "=r"(r0), "=r"(r1), "=r"(r2), "=r"(r3) : "r"(addr))

#define MMA16816(c0, c1, c2, c3, a0, a1, a2, a3, b0, b1) \
    asm volatile("mma.sync.aligned.m16n8k16.row.col.f32.bf16.bf16.f32 " \
        "{%0,%1,%2,%3}, {%4,%5,%6,%7}, {%8,%9}, {%0,%1,%2,%3};" \
        : "+f"(c0), "+f"(c1), "+f"(c2), "+f"(c3) \
        : "r"(a0), "r"(a1), "r"(a2), "r"(a3), "r"(b0), "r"(b1))

// 4-deep x 4-chain dot tree (same fp order as previous passing kernels)
__device__ __forceinline__ float dot16(const float* w, const float* hj) {
    float a0 = fmaf(hj[0], w[0], fmaf(hj[1], w[1], fmaf(hj[2], w[2], hj[3] * w[3])));
    float a1 = fmaf(hj[4], w[4], fmaf(hj[5], w[5], fmaf(hj[6], w[6], hj[7] * w[7])));
    float a2 = fmaf(hj[8], w[8], fmaf(hj[9], w[9], fmaf(hj[10], w[10], hj[11] * w[11])));
    float a3 = fmaf(hj[12], w[12], fmaf(hj[13], w[13], fmaf(hj[14], w[14], hj[15] * w[15])));
    return (a0 + a1) + (a2 + a3);
}

// ---------------- kernel 0: weights -> bf16 hi/lo; zero sync counters -------
__global__ void prep_kernel(const float* __restrict__ Wf, const float* __restrict__ Wi,
                            const float* __restrict__ Wu, const float* __restrict__ Wo) {
    int idx = blockIdx.x * blockDim.x + threadIdx.x;
    if (idx <= NCHUNK) {       // zero ticket + done[]
        if (idx == NCHUNK) g_ticket = 0u;
        else g_done[idx] = 0u;
    }
    if (idx >= NG * DIN) return;
    int n = idx >> 7;
    int k = idx & 127;
    int g = n >> 4, kh = n & 15;
    const float* W = (g == 0) ? Wf : (g == 1) ? Wi : (g == 2) ? Wu : Wo;
    float w = W[kh * FANIN + k];
    uint32_t hp; CVT2(hp, w, 0.f);
    float hf = __uint_as_float(hp << 16);
    uint32_t lp; CVT2(lp, w - hf, 0.f);
    *(unsigned short*)(g_Bh + (size_t)idx * 2) = (unsigned short)(hp & 0xffffu);
    *(unsigned short*)(g_Bl + (size_t)idx * 2) = (unsigned short)(lp & 0xffffu);
}

// ================== persistent fused kernel =================================
// blocks [0, RBLK): recurrence, 8 warps x 2 rows/warp, weights in registers.
// blocks [RBLK, NBLK): persistent gemm, 64-row tiles via g_ticket.
#define PADB 272
#define SM_AH 0
#define SM_AL 17408
#define SM_BH 34816
#define SM_BL 52224
#define GEMM_SMEM 69632

__global__ __launch_bounds__(256, 2) void fused_kernel(
    const float* __restrict__ x,
    const float* __restrict__ Wf, const float* __restrict__ bfv,
    const float* __restrict__ Wi, const float* __restrict__ biv,
    const float* __restrict__ Wu, const float* __restrict__ buv,
    const float* __restrict__ Wo, const float* __restrict__ bov,
    const float* __restrict__ thf, const float* __restrict__ thi,
    const float* __restrict__ thu, const float* __restrict__ tho,
    float* __restrict__ out) {

    extern __shared__ char smem[];
    const int tid = threadIdx.x;
    const int wid = tid >> 5;
    const int lane = tid & 31;

    if (blockIdx.x < RBLK) {
        // ========== recurrence: 2 rows/warp, 4 gates/lane, regs-only ==========
        const int kk  = lane & 15;
        const unsigned FULL = 0xffffffffu;
        const int r = blockIdx.x * 16 + wid * 2 + (lane >> 4);   // batch row
        const int hsrc = lane & 16;                               // own row's h base lane

        // recurrent weights for unit kk, all 4 gates: 64 registers
        float wf[HID], wi_[HID], wu[HID], wo[HID];
#pragma unroll
        for (int j = 0; j < HID; j++) {
            wf[j]  = Wf[kk * FANIN + DIN + j];
            wi_[j] = Wi[kk * FANIN + DIN + j];
            wu[j]  = Wu[kk * FANIN + DIN + j];
            wo[j]  = Wo[kk * FANIN + DIN + j];
        }
        const float addF = bfv[kk] + thf[kk];
        const float addI = biv[kk] + thi[kk];
        const float addU = buv[kk] + thu[kk];
        const float addO = bov[kk] + tho[kk];

        float h = 0.f, c = 0.f;
        const size_t stride = (size_t)BATCH * NG;
        const float* prow = g_pre + (size_t)r * NG + kk;   // + g*16 per gate
        const size_t outIdx = (size_t)r * HID + kk;

        for (int ch = 0; ch < NCHUNK; ch++) {
            while (ldacq(&g_done[ch]) < TILES_PER_CHUNK) __nanosleep(64);

            const float* pbase = prow + (size_t)ch * CHUNK * stride;
            // depth-2 double buffer of the 4 gate pre-activations
            float bf[2][4];
#pragma unroll
            for (int p = 0; p < 2; p++)
#pragma unroll
                for (int g = 0; g < 4; g++)
                    bf[p][g] = pbase[(size_t)p * stride + g * 16];

#pragma unroll 4
            for (int t = 0; t < CHUNK; t++) {
                const int s = t & 1;
                float zF = bf[s][0] + addF;
                float zI = bf[s][1] + addI;
                float zU = bf[s][2] + addU;
                float zO = bf[s][3] + addO;
                int tp = t + 2 < CHUNK ? t + 2 : CHUNK - 1;   // clamped prefetch
#pragma unroll
                for (int g = 0; g < 4; g++)
                    bf[s][g] = pbase[(size_t)tp * stride + g * 16];

                // broadcast own row's h (lanes hsrc..hsrc+15)
                float hj[HID];
#pragma unroll
                for (int j = 0; j < HID; j++)
                    hj[j] = __shfl_sync(FULL, h, hsrc + j);
                zF += dot16(wf, hj);
                zI += dot16(wi_, hj);
                zU += dot16(wu, hj);
                zO += dot16(wo, hj);

                float pF = __cosf(zF);
                float pI = __cosf(zI);
                float pU = __cosf(zU);
                float pO = __cosf(zO);
                // branch-free inclusive cumprod within each 16-lane row half
#pragma unroll
                for (int d = 1; d < 16; d <<= 1) {
                    float uF = __shfl_up_sync(FULL, pF, d);
                    float uI = __shfl_up_sync(FULL, pI, d);
                    float uU = __shfl_up_sync(FULL, pU, d);
                    float uO = __shfl_up_sync(FULL, pO, d);
                    pF *= (kk >= d) ? uF : 1.0f;
                    pI *= (kk >= d) ? uI : 1.0f;
                    pU *= (kk >= d) ? uU : 1.0f;
                    pO *= (kk >= d) ? uO : 1.0f;
                }
                // sigmoid(p) = 1 - 1/(e^p+1); tanh(p) = 1 - 2/(e^{2p}+1)
                float eF = __expf(pF);
                float fG = 1.f - __fdividef(1.f, eF + 1.f);
                float eI = __expf(pI);
                float iG = 1.f - __fdividef(1.f, eI + 1.f);
                float eU = __expf(2.f * pU);
                float gG = fmaf(-2.f, __fdividef(1.f, eU + 1.f), 1.f);
                float eO = __expf(pO);
                float oG = 1.f - __fdividef(1.f, eO + 1.f);

                c = fmaf(fG, c, iG * gG);
                float e2 = __expf(2.f * c);
                float tc = 1.f - __fdividef(2.f, e2 + 1.f);
                h = oG * tc;
                out[(size_t)(ch * CHUNK + t) * (BATCH * HID) + outIdx] = h;
            }
        }
        const size_t off = (size_t)T_LEN * BATCH * HID;
        out[off + outIdx] = h;
        out[off + (size_t)BATCH * HID + outIdx] = c;
        return;
    }

    // ================= persistent GEMM (64-row tiles, work-stealing) =========
    const uint32_t sb = smem_u32(smem);
    __shared__ unsigned s_tile;

    // stage B (hi/lo) once: 64 rows x 256 B into padded rows
    {
        const uint2* bhs = (const uint2*)g_Bh;
        const uint2* bls = (const uint2*)g_Bl;
#pragma unroll
        for (int i = tid; i < 2048; i += 256) {
            int row = i >> 5, chk = i & 31;
            uint32_t off = row * PADB + chk * 8;
            *(uint2*)(smem + SM_BH + off) = bhs[i];
            *(uint2*)(smem + SM_BL + off) = bls[i];
        }
    }

    const int wm = (wid & 3) * 16;        // 4 m-tiles of 16 rows
    const int wn = (wid >> 2) * 32;       // 2 n-halves of 32 cols
    const int rsel = lane & 15;
    const int ksel = (lane >> 4) * 16;
    const int rq = lane >> 2;
    const int cq = (lane & 3) * 2;

    for (;;) {
        if (tid == 0) s_tile = atomicAdd(&g_ticket, 1u);
        __syncthreads();
        unsigned tile = s_tile;
        if (tile >= TOTAL_TILES) break;
        const size_t m0 = (size_t)tile * TILE_M;

        // stage A: fp32 -> bf16 hi/lo split into padded rows (64 x 128)
        {
            const float4* xv = (const float4*)(x + m0 * DIN);
#pragma unroll 4
            for (int i = tid; i < 2048; i += 256) {
                int row = i >> 5;
                int c4  = i & 31;
                float4 v = xv[i];
                uint32_t h01, h23, l01, l23;
                CVT2(h01, v.x, v.y);
                CVT2(h23, v.z, v.w);
                float hx = __uint_as_float(h01 << 16);
                float hy = __uint_as_float(h01 & 0xffff0000u);
                float hz = __uint_as_float(h23 << 16);
                float hw = __uint_as_float(h23 & 0xffff0000u);
                CVT2(l01, v.x - hx, v.y - hy);
                CVT2(l23, v.z - hz, v.w - hw);
                uint32_t off = row * PADB + c4 * 8;
                *(uint2*)(smem + SM_AH + off) = make_uint2(h01, h23);
                *(uint2*)(smem + SM_AL + off) = make_uint2(l01, l23);
            }
        }
        __syncthreads();

        float acc[4][4];
#pragma unroll
        for (int nt = 0; nt < 4; nt++)
#pragma unroll
            for (int q = 0; q < 4; q++) acc[nt][q] = 0.f;

#pragma unroll
        for (int ks = 0; ks < 8; ks++) {
            const uint32_t kbyte = ks * 32 + ksel;
            uint32_t ah[4], al[4];
            {
                uint32_t rowb = (wm + rsel) * PADB + kbyte;
                LDMX4(ah[0], ah[1], ah[2], ah[3], sb + SM_AH + rowb);
                LDMX4(al[0], al[1], al[2], al[3], sb + SM_AL + rowb);
            }
            uint32_t bh[2][4], bl[2][4];
#pragma unroll
            for (int np = 0; np < 2; np++) {
                uint32_t rowb = (wn + np * 16 + rsel) * PADB + kbyte;
                LDMX4(bh[np][0], bh[np][1], bh[np][2], bh[np][3], sb + SM_BH + rowb);
                LDMX4(bl[np][0], bl[np][1], bl[np][2], bl[np][3], sb + SM_BL + rowb);
            }
#pragma unroll
            for (int p = 0; p < 3; p++) {
#pragma unroll
                for (int np = 0; np < 2; np++) {
#pragma unroll
                    for (int o = 0; o < 2; o++) {
                        float* cc = acc[np * 2 + o];
                        const uint32_t* aa = (p == 2) ? al : ah;
                        const uint32_t* bb = (p == 1) ? bl[np] : bh[np];
                        MMA16816(cc[0], cc[1], cc[2], cc[3],
                                 aa[0], aa[1], aa[2], aa[3], bb[o], bb[o + 2]);
                    }
                }
            }
        }

        // epilogue
        {
            size_t row = m0 + wm + rq;
#pragma unroll
            for (int nt = 0; nt < 4; nt++) {
                float* cc = acc[nt];
                int col = wn + nt * 8 + cq;
                *(float2*)(g_pre + row * NG + col)       = make_float2(cc[0], cc[1]);
                *(float2*)(g_pre + (row + 8) * NG + col) = make_float2(cc[2], cc[3]);
            }
        }
        __threadfence();           // pre stores visible before signaling
        __syncthreads();           // all threads' stores+fences done
        if (tid == 0) atomicAdd(&g_done[tile >> 10], 1u);   // 1024 tiles/chunk
        __syncthreads();           // protect s_tile and smem A restaging
    }
}

// ---------------- launch ----------------
extern "C" void kernel_launch(void* const* d_in, const int* in_sizes, int n_in,
                              void* d_out, int out_size) {
    const float* x   = (const float*)d_in[0];
    const float* Wf  = (const float*)d_in[1];
    const float* bfv = (const float*)d_in[2];
    const float* Wi  = (const float*)d_in[3];
    const float* biv = (const float*)d_in[4];
    const float* Wu  = (const float*)d_in[5];
    const float* buv = (const float*)d_in[6];
    const float* Wo  = (const float*)d_in[7];
    const float* bov = (const float*)d_in[8];
    const float* thf = (const float*)d_in[9];
    const float* thi = (const float*)d_in[10];
    const float* thu = (const float*)d_in[11];
    const float* tho = (const float*)d_in[12];
    float* out = (float*)d_out;

    cudaFuncSetAttribute(fused_kernel,
                         cudaFuncAttributeMaxDynamicSharedMemorySize, GEMM_SMEM);

    prep_kernel<<<16, 512>>>(Wf, Wi, Wu, Wo);
    fused_kernel<<<NBLK, 256, GEMM_SMEM>>>(
        x, Wf, bfv, Wi, biv, Wu, buv, Wo, bov,
        thf, thi, thu, tho, out);
}